// round 13
// baseline (speedup 1.0000x reference)
#include <cuda_runtime.h>

#define NB 2
#define NSEQ 2304
#define NH 8
#define HD 32
#define DIMC 256
#define NTAB 9025
#define CPBH 512
#define MROWS (NB*NSEQ)          // 4608
#define NROWS (NB*NH*NSEQ)       // 36864
#define LOG2E 1.4426950408889634f

typedef unsigned long long u64;
typedef unsigned short u16;
typedef unsigned int u32;

// ---- packed f32x2 helpers ----
__device__ __forceinline__ u64 pk(float lo, float hi) {
    u64 r; asm("mov.b64 %0,{%1,%2};" : "=l"(r) : "f"(lo), "f"(hi)); return r;
}
__device__ __forceinline__ void upk(u64 v, float& lo, float& hi) {
    asm("mov.b64 {%0,%1},%2;" : "=f"(lo), "=f"(hi) : "l"(v));
}
__device__ __forceinline__ u64 f2fma(u64 a, u64 b, u64 c) {
    u64 r; asm("fma.rn.f32x2 %0,%1,%2,%3;" : "=l"(r) : "l"(a), "l"(b), "l"(c)); return r;
}

// ---- cp.async ----
__device__ __forceinline__ void cpa16(unsigned smem, const void* g) {
    asm volatile("cp.async.cg.shared.global [%0], [%1], 16;" :: "r"(smem), "l"(g));
}
__device__ __forceinline__ void cpa_commit() {
    asm volatile("cp.async.commit_group;" ::: "memory");
}
__device__ __forceinline__ void cpa_wait1() {
    asm volatile("cp.async.wait_group 1;" ::: "memory");
}

// ---- tf32 mma ----
__device__ __forceinline__ u32 cvt_tf32(float f) {
    u32 u; asm("cvt.rna.tf32.f32 %0,%1;" : "=r"(u) : "f"(f)); return u;
}
__device__ __forceinline__ void mma8(float* c, const u32* a, u32 b0, u32 b1) {
    asm volatile("mma.sync.aligned.m16n8k8.row.col.f32.tf32.tf32.f32 "
                 "{%0,%1,%2,%3},{%4,%5,%6,%7},{%8,%9},{%0,%1,%2,%3};"
                 : "+f"(c[0]), "+f"(c[1]), "+f"(c[2]), "+f"(c[3])
                 : "r"(a[0]), "r"(a[1]), "r"(a[2]), "r"(a[3]), "r"(b0), "r"(b1));
}
__device__ __forceinline__ u32 fu(float f) { return __float_as_uint(f); }

// order-preserving float->u32 encoding (for atomicMax)
__device__ __forceinline__ u32 fenc(float f) {
    u32 u = __float_as_uint(f);
    return (u & 0x80000000u) ? ~u : (u | 0x80000000u);
}
__device__ __forceinline__ float fdec(u32 e) {
    return (e & 0x80000000u) ? __uint_as_float(e ^ 0x80000000u)
                             : __uint_as_float(~e);
}

// -------- device scratch --------
__device__ float g_qkv[MROWS*3*DIMC];
__device__ float g_qhi[NROWS*HD];           // tf32(qn*scale*log2e)
__device__ float g_qlo[NROWS*HD];           // residual
__device__ float g_khi[NROWS*HD];
__device__ float g_klo[NROWS*HD];
__device__ float g_vhi[NROWS*HD];           // tf32(v)
__device__ float g_att[MROWS*DIMC];
__device__ float g_tab[NH*NTAB];            // bias * log2e
__device__ u16   g_idxT[NSEQ*NSEQ];         // TRANSPOSED: [m][n]
__device__ float g_qnm[NROWS];              // ||qn_scaled||
__device__ u32   g_maxb_enc[NH];            // encoded per-head max bias
__device__ int   g_is64 = 1;

// -------- dtype probe + maxb init --------
__global__ void k_flag_scan(const long long* __restrict__ p) {
    if (blockIdx.x == 0 && threadIdx.x < NH) g_maxb_enc[threadIdx.x] = 0u;
    const long total = 524288;
    for (long i = (long)blockIdx.x * blockDim.x + threadIdx.x; i < total;
         i += (long)gridDim.x * blockDim.x) {
        long long v = p[i];
        if (v < 0 || v >= NTAB) g_is64 = 0;
    }
}

// -------- convert int64->u16 AND transpose (tiled) --------
__global__ void k_idx_convert(const long long* __restrict__ p) {
    __shared__ int t[32][33];
    int is64 = g_is64;
    const int* p32 = (const int*)p;
    int bx = blockIdx.x * 32, by = blockIdx.y * 32;
    #pragma unroll
    for (int j = 0; j < 32; j += 8) {
        long src = (long)(by + threadIdx.y + j) * NSEQ + bx + threadIdx.x;
        t[threadIdx.y + j][threadIdx.x] = is64 ? (int)p[src] : p32[src];
    }
    __syncthreads();
    #pragma unroll
    for (int j = 0; j < 32; j += 8) {
        long dst = (long)(bx + threadIdx.y + j) * NSEQ + by + threadIdx.x;
        g_idxT[dst] = (u16)t[threadIdx.x][threadIdx.y + j];
    }
}

// -------- CPB MLP (bias * log2e) + fused per-head max --------
__global__ void k_cpb(const float* __restrict__ tbl, const float* __restrict__ W1,
                      const float* __restrict__ b1, const float* __restrict__ W2,
                      const float* __restrict__ b2) {
    int w = blockIdx.x * 4 + (threadIdx.x >> 5);
    int lane = threadIdx.x & 31;
    if (w >= NTAB) return;
    float c0 = tbl[2*w], c1 = tbl[2*w+1];
    u64 a01 = 0, a23 = 0, a45 = 0, a67 = 0;
    for (int j = lane; j < CPBH; j += 32) {
        float hd = fmaxf(fmaf(c0, W1[2*j], fmaf(c1, W1[2*j+1], b1[j])), 0.f);
        u64 hh = pk(hd, hd);
        a01 = f2fma(hh, pk(W2[0*CPBH+j], W2[1*CPBH+j]), a01);
        a23 = f2fma(hh, pk(W2[2*CPBH+j], W2[3*CPBH+j]), a23);
        a45 = f2fma(hh, pk(W2[4*CPBH+j], W2[5*CPBH+j]), a45);
        a67 = f2fma(hh, pk(W2[6*CPBH+j], W2[7*CPBH+j]), a67);
    }
    float a[8];
    upk(a01, a[0], a[1]); upk(a23, a[2], a[3]);
    upk(a45, a[4], a[5]); upk(a67, a[6], a[7]);
    #pragma unroll
    for (int i = 0; i < 8; i++)
        #pragma unroll
        for (int off = 16; off; off >>= 1)
            a[i] += __shfl_xor_sync(0xffffffffu, a[i], off);
    if (lane == 0) {
        #pragma unroll
        for (int i = 0; i < 8; i++) {
            float tv = (a[i] + b2[i]) * LOG2E;
            g_tab[i*NTAB + w] = tv;
            atomicMax(&g_maxb_enc[i], fenc(tv));
        }
    }
}

// -------- tf32 MMA GEMM (3-pass): C[M][N] = A[M][K] @ W[N][K]^T + bias --------
// tiles 128x64x32, 256 thr / 8 warps; warp = 32x32 sub-tile
#define G_AH 0
#define G_AL 4608
#define G_WH 9216
#define G_WL 11520
#define GEMM_FLOATS 13824
#define GEMM_SMEM (GEMM_FLOATS * 4)          // 55296 B -> 2 CTAs/SM

__global__ void __launch_bounds__(256) k_gemm_t(
        const float* __restrict__ A, const float* __restrict__ W,
        const float* __restrict__ bias, float* __restrict__ C,
        int M, int N, int K) {
    extern __shared__ __align__(16) float sm[];
    float* Ah = sm + G_AH;  float* Al = sm + G_AL;
    float* Wh = sm + G_WH;  float* Wl = sm + G_WL;

    int tid = threadIdx.x;
    int lane = tid & 31, w = tid >> 5;
    int row0 = blockIdx.y * 128, col0 = blockIdx.x * 64;
    int wm = (w & 3) * 32;                    // warp m offset
    int wn = (w >> 2) * 32;                   // warp n offset

    float out[2][4][4];
    #pragma unroll
    for (int im = 0; im < 2; im++)
        #pragma unroll
        for (int in = 0; in < 4; in++)
            #pragma unroll
            for (int j = 0; j < 4; j++) out[im][in][j] = 0.f;

    for (int k0 = 0; k0 < K; k0 += 32) {
        // load + split A tile (128x32 = 1024 float4, 4/thread)
        #pragma unroll
        for (int c = 0; c < 4; c++) {
            int id = c * 256 + tid;
            int r = id >> 3, c4 = (id & 7) << 2;
            float4 v = *(const float4*)(A + (size_t)(row0 + r) * K + k0 + c4);
            float hx = __uint_as_float(cvt_tf32(v.x));
            float hy = __uint_as_float(cvt_tf32(v.y));
            float hz = __uint_as_float(cvt_tf32(v.z));
            float hw = __uint_as_float(cvt_tf32(v.w));
            float* ph = Ah + r*36 + c4;
            float* pl = Al + r*36 + c4;
            ph[0] = hx; ph[1] = hy; ph[2] = hz; ph[3] = hw;
            pl[0] = v.x - hx; pl[1] = v.y - hy; pl[2] = v.z - hz; pl[3] = v.w - hw;
        }
        // load + split W tile (64x32 = 512 float4, 2/thread)
        #pragma unroll
        for (int c = 0; c < 2; c++) {
            int id = c * 256 + tid;
            int r = id >> 3, c4 = (id & 7) << 2;
            float4 v = *(const float4*)(W + (size_t)(col0 + r) * K + k0 + c4);
            float hx = __uint_as_float(cvt_tf32(v.x));
            float hy = __uint_as_float(cvt_tf32(v.y));
            float hz = __uint_as_float(cvt_tf32(v.z));
            float hw = __uint_as_float(cvt_tf32(v.w));
            float* ph = Wh + r*36 + c4;
            float* pl = Wl + r*36 + c4;
            ph[0] = hx; ph[1] = hy; ph[2] = hz; ph[3] = hw;
            pl[0] = v.x - hx; pl[1] = v.y - hy; pl[2] = v.z - hz; pl[3] = v.w - hw;
        }
        __syncthreads();

        #pragma unroll
        for (int kt = 0; kt < 4; kt++) {
            int c0 = kt*8 + (lane & 3);
            u32 ah[2][4], al[2][4];
            #pragma unroll
            for (int im = 0; im < 2; im++) {
                int r0 = wm + im*16 + (lane >> 2), r1 = r0 + 8;
                ah[im][0] = fu(Ah[r0*36 + c0]);
                ah[im][1] = fu(Ah[r1*36 + c0]);
                ah[im][2] = fu(Ah[r0*36 + c0 + 4]);
                ah[im][3] = fu(Ah[r1*36 + c0 + 4]);
                al[im][0] = fu(Al[r0*36 + c0]);
                al[im][1] = fu(Al[r1*36 + c0]);
                al[im][2] = fu(Al[r0*36 + c0 + 4]);
                al[im][3] = fu(Al[r1*36 + c0 + 4]);
            }
            #pragma unroll
            for (int in = 0; in < 4; in++) {
                int nr = wn + in*8 + (lane >> 2);
                u32 bh0 = fu(Wh[nr*36 + c0]), bh1 = fu(Wh[nr*36 + c0 + 4]);
                u32 bl0 = fu(Wl[nr*36 + c0]), bl1 = fu(Wl[nr*36 + c0 + 4]);
                #pragma unroll
                for (int im = 0; im < 2; im++) {
                    mma8(out[im][in], ah[im], bh0, bh1);
                    mma8(out[im][in], al[im], bh0, bh1);
                    mma8(out[im][in], ah[im], bl0, bl1);
                }
            }
        }
        __syncthreads();
    }

    #pragma unroll
    for (int im = 0; im < 2; im++) {
        int r0 = row0 + wm + im*16 + (lane >> 2);
        #pragma unroll
        for (int in = 0; in < 4; in++) {
            int nc = col0 + wn + in*8 + 2*(lane & 3);
            float b0 = bias[nc], b1 = bias[nc + 1];
            *(float2*)(C + (size_t)r0 * N + nc) =
                make_float2(out[im][in][0] + b0, out[im][in][1] + b1);
            *(float2*)(C + (size_t)(r0 + 8) * N + nc) =
                make_float2(out[im][in][2] + b0, out[im][in][3] + b1);
        }
    }
}

// -------- qkv postprocess: normalize/scale + tf32 hi/lo split --------
__global__ void k_qkvpost(const float* __restrict__ temp, const float* __restrict__ seq,
                          const float* __restrict__ emb) {
    int gid = blockIdx.x * 4 + (threadIdx.x >> 5);
    int lane = threadIdx.x & 31;
    int n  = gid % NSEQ;
    int bh = gid / NSEQ;
    int h = bh & 7, b = bh >> 3;
    const float* rp = g_qkv + (size_t)(b * NSEQ + n) * (3 * DIMC);
    float qv = rp[            h * HD + lane];
    float kv = rp[DIMC      + h * HD + lane];
    float vv = rp[2 * DIMC  + h * HD + lane];
    float sq = qv * qv, sk = kv * kv;
    #pragma unroll
    for (int off = 16; off; off >>= 1) {
        sq += __shfl_xor_sync(0xffffffffu, sq, off);
        sk += __shfl_xor_sync(0xffffffffu, sk, off);
    }
    sq = sqrtf(sq); sk = sqrtf(sk);
    float scale = log1pf(expf(temp[h])) * seq[0] * LOG2E;
    float qn = (qv / fmaxf(sq, 1e-12f) + emb[h * HD + lane]) * scale;
    float kn =  kv / fmaxf(sk, 1e-12f);
    size_t o = (size_t)gid * HD + lane;
    float qh = __uint_as_float(cvt_tf32(qn));
    float kh = __uint_as_float(cvt_tf32(kn));
    g_qhi[o] = qh; g_qlo[o] = qn - qh;
    g_khi[o] = kh; g_klo[o] = kn - kh;
    g_vhi[o] = __uint_as_float(cvt_tf32(vv));
    float s2 = qn * qn;
    #pragma unroll
    for (int off = 16; off; off >>= 1)
        s2 += __shfl_xor_sync(0xffffffffu, s2, off);
    if (lane == 0) g_qnm[gid] = sqrtf(s2);
}

// -------- flash attention: tf32 MMA, QT=128, fixed-max softmax --------
#define QT 128
#define KTL 32
#define NT2 (NSEQ/KTL)                        // 72
// float offsets
#define OFF_KH 9056                           // [2][32][36]
#define OFF_KL (OFF_KH + 2304)
#define OFF_VH (OFF_KL + 2304)
#define OFF_IX (OFF_VH + 2304)                // [2][32*128 u16] = 2*2048 floats
#define OFF_P  (OFF_IX + 4096)                // 8 warps x 16x36
#define FLASH_FLOATS (OFF_P + 8*576)          // 24672
#define FLASH_SMEM (FLASH_FLOATS * 4)         // 98688 B -> 2 CTAs/SM

__global__ void __launch_bounds__(256) k_flash() {
    extern __shared__ __align__(16) float dsm[];
    float* tab_s = dsm;

    int tid = threadIdx.x;
    int lane = tid & 31, w = tid >> 5;
    int bh = blockIdx.x;
    int h = bh & 7, b = bh >> 3;
    int n0 = blockIdx.y * QT;

    unsigned smem_base = (unsigned)__cvta_generic_to_shared(dsm);
    size_t kvbase = (size_t)bh * NSEQ * HD;

    auto prefetch = [&](int t) {
        int tt = t < NT2 ? t : NT2 - 1;
        int buf = t & 1;
        int m0 = tt * KTL;
        #pragma unroll
        for (int c = 0; c < 5; c++) {
            int id = c * 256 + tid;
            if (id < 256) {
                int r = id >> 3, cc = id & 7;
                cpa16(smem_base + (OFF_KH + buf*1152 + r*36)*4 + cc*16,
                      g_khi + kvbase + (size_t)(m0 + r)*HD + cc*4);
            } else if (id < 512) {
                int q = id - 256; int r = q >> 3, cc = q & 7;
                cpa16(smem_base + (OFF_KL + buf*1152 + r*36)*4 + cc*16,
                      g_klo + kvbase + (size_t)(m0 + r)*HD + cc*4);
            } else if (id < 768) {
                int q = id - 512; int r = q >> 3, cc = q & 7;
                cpa16(smem_base + (OFF_VH + buf*1152 + r*36)*4 + cc*16,
                      g_vhi + kvbase + (size_t)(m0 + r)*HD + cc*4);
            } else {
                int q = id - 768;
                int r = q >> 4, cc = q & 15;
                cpa16(smem_base + (OFF_IX + buf*2048)*4 + q*16,
                      g_idxT + (size_t)(m0 + r)*NSEQ + n0 + cc*8);
            }
        }
        cpa_commit();
    };

    prefetch(0);
    prefetch(1);

    for (int i = tid; i < NTAB; i += 256) tab_s[i] = g_tab[h * NTAB + i];

    int grow0 = n0 + w * 16 + (lane >> 2), grow1 = grow0 + 8;
    const float* qhb = g_qhi + kvbase;
    const float* qlb = g_qlo + kvbase;
    u32 aqh[4][4], aql[4][4];
    #pragma unroll
    for (int kt = 0; kt < 4; kt++) {
        int c0 = kt*8 + (lane & 3);
        aqh[kt][0] = fu(qhb[(size_t)grow0*HD + c0]);
        aqh[kt][1] = fu(qhb[(size_t)grow1*HD + c0]);
        aqh[kt][2] = fu(qhb[(size_t)grow0*HD + c0 + 4]);
        aqh[kt][3] = fu(qhb[(size_t)grow1*HD + c0 + 4]);
        aql[kt][0] = fu(qlb[(size_t)grow0*HD + c0]);
        aql[kt][1] = fu(qlb[(size_t)grow1*HD + c0]);
        aql[kt][2] = fu(qlb[(size_t)grow0*HD + c0 + 4]);
        aql[kt][3] = fu(qlb[(size_t)grow1*HD + c0 + 4]);
    }

    float mb = fdec(g_maxb_enc[h]);
    float mx0 = g_qnm[bh*NSEQ + grow0] + mb;
    float mx1 = g_qnm[bh*NSEQ + grow1] + mb;

    float out[4][4];
    #pragma unroll
    for (int i = 0; i < 4; i++)
        #pragma unroll
        for (int j = 0; j < 4; j++) out[i][j] = 0.f;
    float l0 = 0.f, l1 = 0.f;

    float* Pw = dsm + OFF_P + w * 576;
    int qloc = w * 16 + (lane >> 2);

    for (int t = 0; t < NT2; t++) {
        int buf = t & 1;
        cpa_wait1();
        __syncthreads();
        const float* KH = dsm + OFF_KH + buf*1152;
        const float* KL = dsm + OFF_KL + buf*1152;
        const float* VH = dsm + OFF_VH + buf*1152;
        const u16*   IX = (const u16*)(dsm + OFF_IX + buf*2048);

        float sc[4][4];
        #pragma unroll
        for (int i = 0; i < 4; i++)
            #pragma unroll
            for (int j = 0; j < 4; j++) sc[i][j] = 0.f;

        #pragma unroll
        for (int nt = 0; nt < 4; nt++) {
            #pragma unroll
            for (int kt = 0; kt < 4; kt++) {
                int krow = nt*8 + (lane >> 2);
                int kd = kt*8 + (lane & 3);
                u32 bh0 = fu(KH[krow*36 + kd]), bh1 = fu(KH[krow*36 + kd + 4]);
                u32 bl0 = fu(KL[krow*36 + kd]), bl1 = fu(KL[krow*36 + kd + 4]);
                mma8(sc[nt], aqh[kt], bh0, bh1);
                mma8(sc[nt], aql[kt], bh0, bh1);
                mma8(sc[nt], aqh[kt], bl0, bl1);
            }
        }

        #pragma unroll
        for (int nt = 0; nt < 4; nt++) {
            int k0 = nt*8 + 2*(lane & 3);
            float b00 = tab_s[(int)IX[k0*QT + qloc]];
            float b01 = tab_s[(int)IX[(k0+1)*QT + qloc]];
            float b10 = tab_s[(int)IX[k0*QT + qloc + 8]];
            float b11 = tab_s[(int)IX[(k0+1)*QT + qloc + 8]];
            float p0 = exp2f(sc[nt][0] + b00 - mx0);
            float p1 = exp2f(sc[nt][1] + b01 - mx0);
            float p2 = exp2f(sc[nt][2] + b10 - mx1);
            float p3 = exp2f(sc[nt][3] + b11 - mx1);
            l0 += p0 + p1;
            l1 += p2 + p3;
            *(float2*)&Pw[(lane>>2)*36 + k0]     = make_float2(p0, p1);
            *(float2*)&Pw[((lane>>2)+8)*36 + k0] = make_float2(p2, p3);
        }
        __syncwarp();

        u32 aPh[4][4], aPl[4][4];
        #pragma unroll
        for (int kt = 0; kt < 4; kt++) {
            int pc = kt*8 + (lane & 3);
            float p00 = Pw[(lane>>2)*36 + pc];
            float p10 = Pw[((lane>>2)+8)*36 + pc];
            float p01 = Pw[(lane>>2)*36 + pc + 4];
            float p11 = Pw[((lane>>2)+8)*36 + pc + 4];
            u32 h00 = cvt_tf32(p00), h10 = cvt_tf32(p10);
            u32 h01 = cvt_tf32(p01), h11 = cvt_tf32(p11);
            aPh[kt][0] = h00; aPh[kt][1] = h10; aPh[kt][2] = h01; aPh[kt][3] = h11;
            aPl[kt][0] = fu(p00 - __uint_as_float(h00));
            aPl[kt][1] = fu(p10 - __uint_as_float(h10));
            aPl[kt][2] = fu(p01 - __uint_as_float(h01));
            aPl[kt][3] = fu(p11 - __uint_as_float(h11));
        }

        #pragma unroll
        for (int dt = 0; dt < 4; dt++) {
            #pragma unroll
            for (int kt = 0; kt < 4; kt++) {
                int vr = kt*8 + (lane & 3);
                int vd = dt*8 + (lane >> 2);
                u32 bvh0 = fu(VH[vr*36 + vd]), bvh1 = fu(VH[(vr+4)*36 + vd]);
                mma8(out[dt], aPh[kt], bvh0, bvh1);
                mma8(out[dt], aPl[kt], bvh0, bvh1);
            }
        }
        __syncthreads();
        prefetch(t + 2);
    }

    l0 += __shfl_xor_sync(0xffffffffu, l0, 1);
    l0 += __shfl_xor_sync(0xffffffffu, l0, 2);
    l1 += __shfl_xor_sync(0xffffffffu, l1, 1);
    l1 += __shfl_xor_sync(0xffffffffu, l1, 2);
    float inv0 = 1.f / l0, inv1 = 1.f / l1;

    #pragma unroll
    for (int dt = 0; dt < 4; dt++) {
        int col = dt*8 + 2*(lane & 3);
        float2 v0 = make_float2(out[dt][0]*inv0, out[dt][1]*inv0);
        float2 v1 = make_float2(out[dt][2]*inv1, out[dt][3]*inv1);
        *(float2*)&g_att[(size_t)(b*NSEQ + grow0)*DIMC + h*HD + col] = v0;
        *(float2*)&g_att[(size_t)(b*NSEQ + grow1)*DIMC + h*HD + col] = v1;
    }
}

extern "C" void kernel_launch(void* const* d_in, const int* in_sizes, int n_in,
                              void* d_out, int out_size) {
    const float*     x     = (const float*)d_in[0];
    const long long* rpi   = (const long long*)d_in[1];
    const float*     rct   = (const float*)d_in[2];
    const float*     seq   = (const float*)d_in[3];
    const float*     Wqkv  = (const float*)d_in[5];
    const float*     bqkv  = (const float*)d_in[6];
    const float*     temp  = (const float*)d_in[7];
    const float*     emb   = (const float*)d_in[8];
    const float*     Wproj = (const float*)d_in[9];
    const float*     bproj = (const float*)d_in[10];
    const float*     W1    = (const float*)d_in[11];
    const float*     b1    = (const float*)d_in[12];
    const float*     W2    = (const float*)d_in[13];
    const float*     b2    = (const float*)d_in[14];
    float* out = (float*)d_out;

    float *p_qkv, *p_att;
    cudaGetSymbolAddress((void**)&p_qkv, g_qkv);
    cudaGetSymbolAddress((void**)&p_att, g_att);

    cudaFuncSetAttribute(k_flash, cudaFuncAttributeMaxDynamicSharedMemorySize,
                         FLASH_SMEM);
    cudaFuncSetAttribute(k_gemm_t, cudaFuncAttributeMaxDynamicSharedMemorySize,
                         GEMM_SMEM);

    k_flag_scan<<<64, 256>>>(rpi);
    k_idx_convert<<<dim3(NSEQ/32, NSEQ/32), dim3(32, 8)>>>(rpi);
    k_cpb<<<(NTAB + 3) / 4, 128>>>(rct, W1, b1, W2, b2);
    k_gemm_t<<<dim3(3 * DIMC / 64, MROWS / 128), 256, GEMM_SMEM>>>(
        x, Wqkv, bqkv, p_qkv, MROWS, 3 * DIMC, DIMC);
    k_qkvpost<<<(NB * NH * NSEQ) / 4, 128>>>(temp, seq, emb);
    k_flash<<<dim3(NB * NH, NSEQ / QT), 256, FLASH_SMEM>>>();
    k_gemm_t<<<dim3(DIMC / 64, MROWS / 128), 256, GEMM_SMEM>>>(
        p_att, Wproj, bproj, out, MROWS, DIMC, DIMC);
}

// round 16
// speedup vs baseline: 1.4986x; 1.4986x over previous
#include <cuda_runtime.h>

#define NB 2
#define NSEQ 2304
#define NH 8
#define HD 32
#define DIMC 256
#define NTAB 9025
#define CPBH 512
#define MROWS (NB*NSEQ)          // 4608
#define NROWS (NB*NH*NSEQ)       // 36864
#define LOG2E 1.4426950408889634f

typedef unsigned long long u64;
typedef unsigned short u16;
typedef unsigned int u32;

// ---- packed f32x2 helpers ----
__device__ __forceinline__ u64 pk(float lo, float hi) {
    u64 r; asm("mov.b64 %0,{%1,%2};" : "=l"(r) : "f"(lo), "f"(hi)); return r;
}
__device__ __forceinline__ void upk(u64 v, float& lo, float& hi) {
    asm("mov.b64 {%0,%1},%2;" : "=f"(lo), "=f"(hi) : "l"(v));
}
__device__ __forceinline__ u64 f2fma(u64 a, u64 b, u64 c) {
    u64 r; asm("fma.rn.f32x2 %0,%1,%2,%3;" : "=l"(r) : "l"(a), "l"(b), "l"(c)); return r;
}

// ---- cp.async ----
__device__ __forceinline__ void cpa16(unsigned smem, const void* g) {
    asm volatile("cp.async.cg.shared.global [%0], [%1], 16;" :: "r"(smem), "l"(g));
}
__device__ __forceinline__ void cpa_commit() {
    asm volatile("cp.async.commit_group;" ::: "memory");
}
__device__ __forceinline__ void cpa_wait1() {
    asm volatile("cp.async.wait_group 1;" ::: "memory");
}

// ---- tf32 mma ----
__device__ __forceinline__ u32 cvt_tf32(float f) {
    u32 u; asm("cvt.rna.tf32.f32 %0,%1;" : "=r"(u) : "f"(f)); return u;
}
__device__ __forceinline__ void mma8(float* c, const u32* a, u32 b0, u32 b1) {
    asm volatile("mma.sync.aligned.m16n8k8.row.col.f32.tf32.tf32.f32 "
                 "{%0,%1,%2,%3},{%4,%5,%6,%7},{%8,%9},{%0,%1,%2,%3};"
                 : "+f"(c[0]), "+f"(c[1]), "+f"(c[2]), "+f"(c[3])
                 : "r"(a[0]), "r"(a[1]), "r"(a[2]), "r"(a[3]), "r"(b0), "r"(b1));
}
__device__ __forceinline__ u32 fu(float f) { return __float_as_uint(f); }

// order-preserving float->u32 encoding (for atomicMax)
__device__ __forceinline__ u32 fenc(float f) {
    u32 u = __float_as_uint(f);
    return (u & 0x80000000u) ? ~u : (u | 0x80000000u);
}
__device__ __forceinline__ float fdec(u32 e) {
    return (e & 0x80000000u) ? __uint_as_float(e ^ 0x80000000u)
                             : __uint_as_float(~e);
}

// -------- device scratch --------
__device__ float g_qkv[MROWS*3*DIMC];
__device__ float g_qhi[NROWS*HD];           // tf32(qn*scale*log2e)
__device__ float g_qlo[NROWS*HD];           // residual
__device__ float g_k[NROWS*HD];             // raw normalized k
__device__ float g_v[NROWS*HD];             // raw v
__device__ float g_att[MROWS*DIMC];
__device__ float g_tab[NH*NTAB];            // bias * log2e
__device__ u16   g_idxT[NSEQ*NSEQ];         // TRANSPOSED: [m][n]
__device__ float g_qnm[NROWS];              // ||qn_scaled||
__device__ u32   g_maxb_enc[NH];            // encoded per-head max bias
__device__ int   g_is64 = 1;

// -------- dtype probe + maxb init --------
__global__ void k_flag_scan(const long long* __restrict__ p) {
    if (blockIdx.x == 0 && threadIdx.x < NH) g_maxb_enc[threadIdx.x] = 0u;
    const long total = 524288;
    for (long i = (long)blockIdx.x * blockDim.x + threadIdx.x; i < total;
         i += (long)gridDim.x * blockDim.x) {
        long long v = p[i];
        if (v < 0 || v >= NTAB) g_is64 = 0;
    }
}

// -------- convert int64->u16 AND transpose (tiled) --------
__global__ void k_idx_convert(const long long* __restrict__ p) {
    __shared__ int t[32][33];
    int is64 = g_is64;
    const int* p32 = (const int*)p;
    int bx = blockIdx.x * 32, by = blockIdx.y * 32;
    #pragma unroll
    for (int j = 0; j < 32; j += 8) {
        long src = (long)(by + threadIdx.y + j) * NSEQ + bx + threadIdx.x;
        t[threadIdx.y + j][threadIdx.x] = is64 ? (int)p[src] : p32[src];
    }
    __syncthreads();
    #pragma unroll
    for (int j = 0; j < 32; j += 8) {
        long dst = (long)(bx + threadIdx.y + j) * NSEQ + by + threadIdx.x;
        g_idxT[dst] = (u16)t[threadIdx.x][threadIdx.y + j];
    }
}

// -------- CPB MLP (bias * log2e) + fused per-head max --------
__global__ void k_cpb(const float* __restrict__ tbl, const float* __restrict__ W1,
                      const float* __restrict__ b1, const float* __restrict__ W2,
                      const float* __restrict__ b2) {
    int w = blockIdx.x * 4 + (threadIdx.x >> 5);
    int lane = threadIdx.x & 31;
    if (w >= NTAB) return;
    float c0 = tbl[2*w], c1 = tbl[2*w+1];
    u64 a01 = 0, a23 = 0, a45 = 0, a67 = 0;
    for (int j = lane; j < CPBH; j += 32) {
        float hd = fmaxf(fmaf(c0, W1[2*j], fmaf(c1, W1[2*j+1], b1[j])), 0.f);
        u64 hh = pk(hd, hd);
        a01 = f2fma(hh, pk(W2[0*CPBH+j], W2[1*CPBH+j]), a01);
        a23 = f2fma(hh, pk(W2[2*CPBH+j], W2[3*CPBH+j]), a23);
        a45 = f2fma(hh, pk(W2[4*CPBH+j], W2[5*CPBH+j]), a45);
        a67 = f2fma(hh, pk(W2[6*CPBH+j], W2[7*CPBH+j]), a67);
    }
    float a[8];
    upk(a01, a[0], a[1]); upk(a23, a[2], a[3]);
    upk(a45, a[4], a[5]); upk(a67, a[6], a[7]);
    #pragma unroll
    for (int i = 0; i < 8; i++)
        #pragma unroll
        for (int off = 16; off; off >>= 1)
            a[i] += __shfl_xor_sync(0xffffffffu, a[i], off);
    if (lane == 0) {
        #pragma unroll
        for (int i = 0; i < 8; i++) {
            float tv = (a[i] + b2[i]) * LOG2E;
            g_tab[i*NTAB + w] = tv;
            atomicMax(&g_maxb_enc[i], fenc(tv));
        }
    }
}

// -------- tiled fp32 GEMM with packed FFMA2 (round-12 proven) --------
#define BM 128
#define BN 64
#define BK 16
__global__ void __launch_bounds__(256) k_gemm(
        const float* __restrict__ A, const float* __restrict__ W,
        const float* __restrict__ bias, float* __restrict__ C,
        int M, int N, int K) {
    __shared__ __align__(16) float As[BK][BM];
    __shared__ __align__(16) float Bs[BK][BN];
    int tid = threadIdx.x;
    int row0 = blockIdx.y * BM, col0 = blockIdx.x * BN;
    int ty = tid >> 4, tx = tid & 15;
    u64 acc2[4][4];
    #pragma unroll
    for (int i = 0; i < 4; i++)
        #pragma unroll
        for (int j = 0; j < 4; j++) acc2[i][j] = 0ull;

    for (int k0 = 0; k0 < K; k0 += BK) {
        #pragma unroll
        for (int jj = 0; jj < 2; jj++) {
            int f = tid + jj * 256;
            int ar = f >> 2, ac = (f & 3) << 2;
            float4 v = *(const float4*)(A + (size_t)(row0 + ar) * K + k0 + ac);
            As[ac  ][ar] = v.x; As[ac+1][ar] = v.y;
            As[ac+2][ar] = v.z; As[ac+3][ar] = v.w;
        }
        {
            int f = tid;
            int br = f >> 2, bc = (f & 3) << 2;
            float4 v = *(const float4*)(W + (size_t)(col0 + br) * K + k0 + bc);
            Bs[bc  ][br] = v.x; Bs[bc+1][br] = v.y;
            Bs[bc+2][br] = v.z; Bs[bc+3][br] = v.w;
        }
        __syncthreads();
        #pragma unroll
        for (int kk = 0; kk < BK; kk++) {
            ulonglong2 aA = *(const ulonglong2*)&As[kk][ty*8];
            ulonglong2 aB = *(const ulonglong2*)&As[kk][ty*8 + 4];
            u64 a2[4] = {aA.x, aA.y, aB.x, aB.y};
            float4 bq = *(const float4*)&Bs[kk][tx*4];
            u64 bd[4] = {pk(bq.x,bq.x), pk(bq.y,bq.y), pk(bq.z,bq.z), pk(bq.w,bq.w)};
            #pragma unroll
            for (int i = 0; i < 4; i++)
                #pragma unroll
                for (int j = 0; j < 4; j++)
                    acc2[i][j] = f2fma(a2[i], bd[j], acc2[i][j]);
        }
        __syncthreads();
    }
    float4 bb = *(const float4*)(bias + col0 + tx*4);
    #pragma unroll
    for (int i = 0; i < 4; i++) {
        float lo[4], hi[4];
        #pragma unroll
        for (int j = 0; j < 4; j++) upk(acc2[i][j], lo[j], hi[j]);
        float4 o0, o1;
        o0.x = lo[0]+bb.x; o0.y = lo[1]+bb.y; o0.z = lo[2]+bb.z; o0.w = lo[3]+bb.w;
        o1.x = hi[0]+bb.x; o1.y = hi[1]+bb.y; o1.z = hi[2]+bb.z; o1.w = hi[3]+bb.w;
        *(float4*)(C + (size_t)(row0 + ty*8 + 2*i    ) * N + col0 + tx*4) = o0;
        *(float4*)(C + (size_t)(row0 + ty*8 + 2*i + 1) * N + col0 + tx*4) = o1;
    }
}

// -------- qkv postprocess: normalize/scale; q split hi/lo, k/v raw --------
__global__ void k_qkvpost(const float* __restrict__ temp, const float* __restrict__ seq,
                          const float* __restrict__ emb) {
    int gid = blockIdx.x * 4 + (threadIdx.x >> 5);
    int lane = threadIdx.x & 31;
    int n  = gid % NSEQ;
    int bh = gid / NSEQ;
    int h = bh & 7, b = bh >> 3;
    const float* rp = g_qkv + (size_t)(b * NSEQ + n) * (3 * DIMC);
    float qv = rp[            h * HD + lane];
    float kv = rp[DIMC      + h * HD + lane];
    float vv = rp[2 * DIMC  + h * HD + lane];
    float sq = qv * qv, sk = kv * kv;
    #pragma unroll
    for (int off = 16; off; off >>= 1) {
        sq += __shfl_xor_sync(0xffffffffu, sq, off);
        sk += __shfl_xor_sync(0xffffffffu, sk, off);
    }
    sq = sqrtf(sq); sk = sqrtf(sk);
    float scale = log1pf(expf(temp[h])) * seq[0] * LOG2E;
    float qn = (qv / fmaxf(sq, 1e-12f) + emb[h * HD + lane]) * scale;
    float kn =  kv / fmaxf(sk, 1e-12f);
    size_t o = (size_t)gid * HD + lane;
    float qh = __uint_as_float(cvt_tf32(qn));
    g_qhi[o] = qh; g_qlo[o] = qn - qh;
    g_k[o] = kn;
    g_v[o] = vv;
    float s2 = qn * qn;
    #pragma unroll
    for (int off = 16; off; off >>= 1)
        s2 += __shfl_xor_sync(0xffffffffu, s2, off);
    if (lane == 0) g_qnm[gid] = sqrtf(s2);
}

// -------- flash attention: tf32 MMA, raw K/V + in-register split --------
#define QT 128
#define KTL 32
#define NT2 (NSEQ/KTL)                        // 72
// float offsets
#define OFF_K  9056                           // [2][32][36] raw k
#define OFF_V  (OFF_K + 2304)                 // [2][32][36] raw v
#define OFF_IX (OFF_V + 2304)                 // [2][32*128 u16] = 2*2048 floats
#define OFF_P  (OFF_IX + 4096)                // 8 warps x 16x36
#define FLASH_FLOATS (OFF_P + 8*576)          // 22368
#define FLASH_SMEM (FLASH_FLOATS * 4)         // 89472 B -> 2 CTAs/SM

__global__ void __launch_bounds__(256) k_flash() {
    extern __shared__ __align__(16) float dsm[];
    float* tab_s = dsm;

    int tid = threadIdx.x;
    int lane = tid & 31, w = tid >> 5;
    int bh = blockIdx.x;
    int h = bh & 7, b = bh >> 3;
    int n0 = blockIdx.y * QT;

    unsigned smem_base = (unsigned)__cvta_generic_to_shared(dsm);
    size_t kvbase = (size_t)bh * NSEQ * HD;

    // 4 chunks of 16B per thread: K(256) V(256) IX(512)
    auto prefetch = [&](int t) {
        int tt = t < NT2 ? t : NT2 - 1;
        int buf = t & 1;
        int m0 = tt * KTL;
        #pragma unroll
        for (int c = 0; c < 4; c++) {
            int id = c * 256 + tid;
            if (id < 256) {
                int r = id >> 3, cc = id & 7;
                cpa16(smem_base + (OFF_K + buf*1152 + r*36)*4 + cc*16,
                      g_k + kvbase + (size_t)(m0 + r)*HD + cc*4);
            } else if (id < 512) {
                int q = id - 256; int r = q >> 3, cc = q & 7;
                cpa16(smem_base + (OFF_V + buf*1152 + r*36)*4 + cc*16,
                      g_v + kvbase + (size_t)(m0 + r)*HD + cc*4);
            } else {
                int q = id - 512;                 // 0..511
                int r = q >> 4, cc = q & 15;
                cpa16(smem_base + (OFF_IX + buf*2048)*4 + q*16,
                      g_idxT + (size_t)(m0 + r)*NSEQ + n0 + cc*8);
            }
        }
        cpa_commit();
    };

    prefetch(0);
    prefetch(1);

    for (int i = tid; i < NTAB; i += 256) tab_s[i] = g_tab[h * NTAB + i];

    int grow0 = n0 + w * 16 + (lane >> 2), grow1 = grow0 + 8;
    const float* qhb = g_qhi + kvbase;
    const float* qlb = g_qlo + kvbase;
    u32 aqh[4][4], aql[4][4];
    #pragma unroll
    for (int kt = 0; kt < 4; kt++) {
        int c0 = kt*8 + (lane & 3);
        aqh[kt][0] = fu(qhb[(size_t)grow0*HD + c0]);
        aqh[kt][1] = fu(qhb[(size_t)grow1*HD + c0]);
        aqh[kt][2] = fu(qhb[(size_t)grow0*HD + c0 + 4]);
        aqh[kt][3] = fu(qhb[(size_t)grow1*HD + c0 + 4]);
        aql[kt][0] = fu(qlb[(size_t)grow0*HD + c0]);
        aql[kt][1] = fu(qlb[(size_t)grow1*HD + c0]);
        aql[kt][2] = fu(qlb[(size_t)grow0*HD + c0 + 4]);
        aql[kt][3] = fu(qlb[(size_t)grow1*HD + c0 + 4]);
    }

    float mb = fdec(g_maxb_enc[h]);
    float mx0 = g_qnm[bh*NSEQ + grow0] + mb;
    float mx1 = g_qnm[bh*NSEQ + grow1] + mb;

    float out[4][4];
    #pragma unroll
    for (int i = 0; i < 4; i++)
        #pragma unroll
        for (int j = 0; j < 4; j++) out[i][j] = 0.f;
    float l0 = 0.f, l1 = 0.f;

    float* Pw = dsm + OFF_P + w * 576;
    int qloc = w * 16 + (lane >> 2);

    for (int t = 0; t < NT2; t++) {
        int buf = t & 1;
        cpa_wait1();
        __syncthreads();
        const float* KS = dsm + OFF_K + buf*1152;
        const float* VS = dsm + OFF_V + buf*1152;
        const u16*   IX = (const u16*)(dsm + OFF_IX + buf*2048);

        float sc[4][4];
        #pragma unroll
        for (int i = 0; i < 4; i++)
            #pragma unroll
            for (int j = 0; j < 4; j++) sc[i][j] = 0.f;

        // S = Qh*Kh + Ql*Kh + Qh*Kl  (K split in registers from raw)
        #pragma unroll
        for (int nt = 0; nt < 4; nt++) {
            #pragma unroll
            for (int kt = 0; kt < 4; kt++) {
                int krow = nt*8 + (lane >> 2);
                int kd = kt*8 + (lane & 3);
                float kr0 = KS[krow*36 + kd], kr1 = KS[krow*36 + kd + 4];
                float kh0 = __uint_as_float(cvt_tf32(kr0));
                float kh1 = __uint_as_float(cvt_tf32(kr1));
                u32 bh0 = fu(kh0), bh1 = fu(kh1);
                u32 bl0 = fu(kr0 - kh0), bl1 = fu(kr1 - kh1);
                mma8(sc[nt], aqh[kt], bh0, bh1);
                mma8(sc[nt], aql[kt], bh0, bh1);
                mma8(sc[nt], aqh[kt], bl0, bl1);
            }
        }

        // bias + exp2 + row-sum + stage P
        #pragma unroll
        for (int nt = 0; nt < 4; nt++) {
            int k0 = nt*8 + 2*(lane & 3);
            float b00 = tab_s[(int)IX[k0*QT + qloc]];
            float b01 = tab_s[(int)IX[(k0+1)*QT + qloc]];
            float b10 = tab_s[(int)IX[k0*QT + qloc + 8]];
            float b11 = tab_s[(int)IX[(k0+1)*QT + qloc + 8]];
            float p0 = exp2f(sc[nt][0] + b00 - mx0);
            float p1 = exp2f(sc[nt][1] + b01 - mx0);
            float p2 = exp2f(sc[nt][2] + b10 - mx1);
            float p3 = exp2f(sc[nt][3] + b11 - mx1);
            l0 += p0 + p1;
            l1 += p2 + p3;
            *(float2*)&Pw[(lane>>2)*36 + k0]     = make_float2(p0, p1);
            *(float2*)&Pw[((lane>>2)+8)*36 + k0] = make_float2(p2, p3);
        }
        __syncwarp();

        // reload P as A-frags, split tf32
        u32 aPh[4][4], aPl[4][4];
        #pragma unroll
        for (int kt = 0; kt < 4; kt++) {
            int pc = kt*8 + (lane & 3);
            float p00 = Pw[(lane>>2)*36 + pc];
            float p10 = Pw[((lane>>2)+8)*36 + pc];
            float p01 = Pw[(lane>>2)*36 + pc + 4];
            float p11 = Pw[((lane>>2)+8)*36 + pc + 4];
            u32 h00 = cvt_tf32(p00), h10 = cvt_tf32(p10);
            u32 h01 = cvt_tf32(p01), h11 = cvt_tf32(p11);
            aPh[kt][0] = h00; aPh[kt][1] = h10; aPh[kt][2] = h01; aPh[kt][3] = h11;
            aPl[kt][0] = fu(p00 - __uint_as_float(h00));
            aPl[kt][1] = fu(p10 - __uint_as_float(h10));
            aPl[kt][2] = fu(p01 - __uint_as_float(h01));
            aPl[kt][3] = fu(p11 - __uint_as_float(h11));
        }

        // O += Ph*Vh + Pl*Vh   (Vh = tf32(raw v), cvt in registers)
        #pragma unroll
        for (int dt = 0; dt < 4; dt++) {
            #pragma unroll
            for (int kt = 0; kt < 4; kt++) {
                int vr = kt*8 + (lane & 3);
                int vd = dt*8 + (lane >> 2);
                u32 bvh0 = cvt_tf32(VS[vr*36 + vd]);
                u32 bvh1 = cvt_tf32(VS[(vr+4)*36 + vd]);
                mma8(out[dt], aPh[kt], bvh0, bvh1);
                mma8(out[dt], aPl[kt], bvh0, bvh1);
            }
        }
        __syncthreads();
        prefetch(t + 2);
    }

    l0 += __shfl_xor_sync(0xffffffffu, l0, 1);
    l0 += __shfl_xor_sync(0xffffffffu, l0, 2);
    l1 += __shfl_xor_sync(0xffffffffu, l1, 1);
    l1 += __shfl_xor_sync(0xffffffffu, l1, 2);
    float inv0 = 1.f / l0, inv1 = 1.f / l1;

    #pragma unroll
    for (int dt = 0; dt < 4; dt++) {
        int col = dt*8 + 2*(lane & 3);
        float2 v0 = make_float2(out[dt][0]*inv0, out[dt][1]*inv0);
        float2 v1 = make_float2(out[dt][2]*inv1, out[dt][3]*inv1);
        *(float2*)&g_att[(size_t)(b*NSEQ + grow0)*DIMC + h*HD + col] = v0;
        *(float2*)&g_att[(size_t)(b*NSEQ + grow1)*DIMC + h*HD + col] = v1;
    }
}

extern "C" void kernel_launch(void* const* d_in, const int* in_sizes, int n_in,
                              void* d_out, int out_size) {
    const float*     x     = (const float*)d_in[0];
    const long long* rpi   = (const long long*)d_in[1];
    const float*     rct   = (const float*)d_in[2];
    const float*     seq   = (const float*)d_in[3];
    const float*     Wqkv  = (const float*)d_in[5];
    const float*     bqkv  = (const float*)d_in[6];
    const float*     temp  = (const float*)d_in[7];
    const float*     emb   = (const float*)d_in[8];
    const float*     Wproj = (const float*)d_in[9];
    const float*     bproj = (const float*)d_in[10];
    const float*     W1    = (const float*)d_in[11];
    const float*     b1    = (const float*)d_in[12];
    const float*     W2    = (const float*)d_in[13];
    const float*     b2    = (const float*)d_in[14];
    float* out = (float*)d_out;

    float *p_qkv, *p_att;
    cudaGetSymbolAddress((void**)&p_qkv, g_qkv);
    cudaGetSymbolAddress((void**)&p_att, g_att);

    cudaFuncSetAttribute(k_flash, cudaFuncAttributeMaxDynamicSharedMemorySize,
                         FLASH_SMEM);

    k_flag_scan<<<64, 256>>>(rpi);
    k_idx_convert<<<dim3(NSEQ/32, NSEQ/32), dim3(32, 8)>>>(rpi);
    k_cpb<<<(NTAB + 3) / 4, 128>>>(rct, W1, b1, W2, b2);
    k_gemm<<<dim3(3 * DIMC / BN, MROWS / BM), 256>>>(x, Wqkv, bqkv, p_qkv,
                                                     MROWS, 3 * DIMC, DIMC);
    k_qkvpost<<<(NB * NH * NSEQ) / 4, 128>>>(temp, seq, emb);
    k_flash<<<dim3(NB * NH, NSEQ / QT), 256, FLASH_SMEM>>>();
    k_gemm<<<dim3(DIMC / BN, MROWS / BM), 256>>>(p_att, Wproj, bproj, out,
                                                 MROWS, DIMC, DIMC);
}